// round 13
// baseline (speedup 1.0000x reference)
#include <cuda_runtime.h>
#include <cstdint>

#define N_ATOMS_MAX 200000
#define N_IMAGES_MAX 128

// Zero-initialized at module load. Every run restores the all-zero invariant:
//  - atom_kernel writes zeros back to each scratch row it consumes
//  - finalize_kernel re-zeros g_virial
__device__ __align__(16) float g_scratch[(size_t)N_ATOMS_MAX * 12];
__device__ __align__(16) float g_virial[N_IMAGES_MAX * 12];

__device__ __forceinline__ void red4(float* p, float a, float b, float c, float d) {
    asm volatile("red.global.add.v4.f32 [%0], {%1,%2,%3,%4};"
                 :: "l"(p), "f"(a), "f"(b), "f"(c), "f"(d) : "memory");
}

__device__ __forceinline__ float4 ldcs4(const float4* p) { return __ldcs(p); }
__device__ __forceinline__ int4   ldcs4i(const int4* p)  { return __ldcs(p); }

__device__ __forceinline__ void process_edge(
    float dx, float dy, float dz,
    float gx, float gy, float gz,
    int i, int j)
{
    // i endpoint: 3 force comps + 9 virial comps packed into exactly 3 v4 reds
    float* si = g_scratch + (size_t)i * 12;
    red4(si + 0, gx,      gy,      gz,      dx * gx);
    red4(si + 4, dx * gy, dx * gz, dy * gx, dy * gy);
    red4(si + 8, dy * gz, dz * gx, dz * gy, dz * gz);
    // j endpoint: force -= g
    float* sj = g_scratch + (size_t)j * 12;
    red4(sj + 0, -gx, -gy, -gz, 0.f);
}

// Software-pipelined grid-stride: each thread handles many quads (4 edges),
// issuing the next quad's loads before firing the current quad's reds.
// REDs are fire-and-forget, so the warp streams RMWs into L2 continuously.
__global__ __launch_bounds__(256) void edge_kernel(
    const float* __restrict__ edge_diff,
    const float* __restrict__ dE,
    const int* __restrict__ edge_idx,
    int n_edges)
{
    const float4* diff4 = (const float4*)edge_diff;
    const float4* dE4   = (const float4*)dE;
    const int4*   idx4  = (const int4*)edge_idx;

    int T   = gridDim.x * blockDim.x;
    int gid = blockIdx.x * blockDim.x + threadIdx.x;
    int nq  = n_edges >> 2;   // full quads

    // scalar tail (n_edges % 4), handled once
    if (gid == 0) {
        for (int e = nq * 4; e < n_edges; e++) {
            process_edge(__ldcs(edge_diff + 3 * e + 0), __ldcs(edge_diff + 3 * e + 1),
                         __ldcs(edge_diff + 3 * e + 2),
                         __ldcs(dE + 3 * e + 0), __ldcs(dE + 3 * e + 1), __ldcs(dE + 3 * e + 2),
                         __ldcs(edge_idx + 2 * e + 0), __ldcs(edge_idx + 2 * e + 1));
        }
    }

    float4 d0, d1, d2, g0, g1, g2;
    int4 i0, i1;

    int q = gid;
    bool valid = (q < nq);
    if (valid) {
        d0 = ldcs4(diff4 + 3 * q + 0);
        d1 = ldcs4(diff4 + 3 * q + 1);
        d2 = ldcs4(diff4 + 3 * q + 2);
        g0 = ldcs4(dE4 + 3 * q + 0);
        g1 = ldcs4(dE4 + 3 * q + 1);
        g2 = ldcs4(dE4 + 3 * q + 2);
        i0 = ldcs4i(idx4 + 2 * q + 0);
        i1 = ldcs4i(idx4 + 2 * q + 1);
    }

    while (valid) {
        // stash current batch
        float4 e0 = d0, e1 = d1, e2 = d2;
        float4 h0 = g0, h1 = g1, h2 = g2;
        int4 j0 = i0, j1 = i1;

        int qn = q + T;
        bool nvalid = (qn < nq);
        if (nvalid) {
            // prefetch next batch BEFORE issuing reds for the current one
            d0 = ldcs4(diff4 + 3 * qn + 0);
            d1 = ldcs4(diff4 + 3 * qn + 1);
            d2 = ldcs4(diff4 + 3 * qn + 2);
            g0 = ldcs4(dE4 + 3 * qn + 0);
            g1 = ldcs4(dE4 + 3 * qn + 1);
            g2 = ldcs4(dE4 + 3 * qn + 2);
            i0 = ldcs4i(idx4 + 2 * qn + 0);
            i1 = ldcs4i(idx4 + 2 * qn + 1);
        }

        process_edge(e0.x, e0.y, e0.z, h0.x, h0.y, h0.z, j0.x, j0.y);
        process_edge(e0.w, e1.x, e1.y, h0.w, h1.x, h1.y, j0.z, j0.w);
        process_edge(e1.z, e1.w, e2.x, h1.z, h1.w, h2.x, j1.x, j1.y);
        process_edge(e2.y, e2.z, e2.w, h2.y, h2.z, h2.w, j1.z, j1.w);

        q = qn;
        valid = nvalid;
    }
}

// 2 atoms per thread. image_idx sorted -> 64-atom warp span almost always image-uniform.
__global__ __launch_bounds__(256) void atom_kernel(
    const int* __restrict__ image_idx,
    float* __restrict__ out,
    int n_atoms)
{
    int t = blockIdx.x * blockDim.x + threadIdx.x;
    int a0 = 2 * t;
    const float4 z4 = make_float4(0.f, 0.f, 0.f, 0.f);

    int my_img = -1;
    float v[9];
#pragma unroll
    for (int k = 0; k < 9; k++) v[k] = 0.f;

    bool active = (a0 < n_atoms);
    if (active) {
        bool has2 = (a0 + 1 < n_atoms);

        float4* s = (float4*)(g_scratch + (size_t)a0 * 12);
        float4 r0 = s[0], r1 = s[1], r2 = s[2];
        float4 r3 = z4, r4 = z4, r5 = z4;
        if (has2) { r3 = s[3]; r4 = s[4]; r5 = s[5]; }

        s[0] = z4; s[1] = z4; s[2] = z4;
        if (has2) { s[3] = z4; s[4] = z4; s[5] = z4; }

        float2* o = (float2*)(out + (size_t)a0 * 3);
        o[0] = make_float2(r0.x, r0.y);
        if (has2) {
            o[1] = make_float2(r0.z, r3.x);
            o[2] = make_float2(r3.y, r3.z);
        } else {
            out[3 * a0 + 2] = r0.z;
        }

        int im0 = image_idx[a0];
        int im1 = has2 ? image_idx[a0 + 1] : im0;

        if (im0 == im1) {
            my_img = im0;
            v[0] = r0.w + r3.w; v[1] = r1.x + r4.x; v[2] = r1.y + r4.y;
            v[3] = r1.z + r4.z; v[4] = r1.w + r4.w; v[5] = r2.x + r5.x;
            v[6] = r2.y + r5.y; v[7] = r2.z + r5.z; v[8] = r2.w + r5.w;
        } else {
            float* ga = g_virial + (size_t)im0 * 12;
            red4(ga + 0, r0.w, r1.x, r1.y, r1.z);
            red4(ga + 4, r1.w, r2.x, r2.y, r2.z);
            red4(ga + 8, r2.w, 0.f, 0.f, 0.f);
            float* gb = g_virial + (size_t)im1 * 12;
            red4(gb + 0, r3.w, r4.x, r4.y, r4.z);
            red4(gb + 4, r4.w, r5.x, r5.y, r5.z);
            red4(gb + 8, r5.w, 0.f, 0.f, 0.f);
        }
    }

    int lane = threadIdx.x & 31;
    int img0 = __shfl_sync(0xFFFFFFFFu, my_img, 0);
    bool uniform = __all_sync(0xFFFFFFFFu, my_img == img0) && (img0 >= 0);

    if (uniform) {
        // 4-stage butterfly (16,8,4,2): lane0 = even-lane sum, lane1 = odd-lane sum
#pragma unroll
        for (int k = 0; k < 9; k++) {
#pragma unroll
            for (int off = 16; off > 1; off >>= 1)
                v[k] += __shfl_xor_sync(0xFFFFFFFFu, v[k], off);
        }
        if (lane < 2) {
            float* g = g_virial + (size_t)img0 * 12;
            red4(g + 0, v[0], v[1], v[2], v[3]);
            red4(g + 4, v[4], v[5], v[6], v[7]);
            red4(g + 8, v[8], 0.f, 0.f, 0.f);
        }
    } else if (my_img >= 0) {
        float* g = g_virial + (size_t)my_img * 12;
        red4(g + 0, v[0], v[1], v[2], v[3]);
        red4(g + 4, v[4], v[5], v[6], v[7]);
        red4(g + 8, v[8], 0.f, 0.f, 0.f);
    }
}

__global__ void finalize_kernel(
    const float* __restrict__ cell,
    float* __restrict__ out,
    int n_atoms, int n_images)
{
    int i = threadIdx.x;
    if (i >= n_images) return;

    const float* c = cell + i * 9;
    float a0 = c[0], a1 = c[1], a2 = c[2];
    float b0 = c[3], b1 = c[4], b2 = c[5];
    float c0 = c[6], c1 = c[7], c2 = c[8];
    float x0 = b1 * c2 - b2 * c1;
    float x1 = b2 * c0 - b0 * c2;
    float x2 = b0 * c1 - b1 * c0;
    float vol = a0 * x0 + a1 * x1 + a2 * x2;
    float inv = -1.0f / vol;

    float* gv = g_virial + (size_t)i * 12;
    float* vir_out    = out + (size_t)n_atoms * 3 + (size_t)i * 9;
    float* stress_out = out + (size_t)n_atoms * 3 + (size_t)n_images * 9 + (size_t)i * 9;
    float vv[9];
#pragma unroll
    for (int k = 0; k < 9; k++) vv[k] = gv[k];
#pragma unroll
    for (int k = 0; k < 9; k++) {
        vir_out[k] = vv[k];
        stress_out[k] = vv[k] * inv;
    }
    float4* gv4 = (float4*)gv;
    gv4[0] = make_float4(0.f, 0.f, 0.f, 0.f);
    gv4[1] = make_float4(0.f, 0.f, 0.f, 0.f);
    gv4[2] = make_float4(0.f, 0.f, 0.f, 0.f);
}

extern "C" void kernel_launch(void* const* d_in, const int* in_sizes, int n_in,
                              void* d_out, int out_size)
{
    const float* edge_diff = (const float*)d_in[0];
    const float* dE        = (const float*)d_in[1];
    const float* cell      = (const float*)d_in[2];
    const int*   edge_idx  = (const int*)d_in[3];
    const int*   image_idx = (const int*)d_in[4];

    int n_edges  = in_sizes[0] / 3;
    int n_atoms  = in_sizes[4];
    int n_images = in_sizes[2] / 9;
    float* out = (float*)d_out;

    // persistent-style grid: ~4 blocks per SM, each thread pipelines ~10 quads
    edge_kernel<<<592, 256>>>(edge_diff, dE, edge_idx, n_edges);

    int n_t = (n_atoms + 1) / 2;
    atom_kernel<<<(n_t + 255) / 256, 256>>>(image_idx, out, n_atoms);

    finalize_kernel<<<1, 128>>>(cell, out, n_atoms, n_images);
}

// round 14
// speedup vs baseline: 1.1304x; 1.1304x over previous
#include <cuda_runtime.h>
#include <cstdint>

#define N_ATOMS_MAX 200000
#define N_IMAGES_MAX 128

// Zero-initialized at module load. Every run restores the all-zero invariant:
//  - atom_kernel writes zeros back to each scratch row it consumes
//  - finalize_kernel re-zeros g_virial
__device__ __align__(16) float g_scratch[(size_t)N_ATOMS_MAX * 12];
__device__ __align__(16) float g_virial[N_IMAGES_MAX * 12];

__device__ __forceinline__ void red4(float* p, float a, float b, float c, float d) {
    asm volatile("red.global.add.v4.f32 [%0], {%1,%2,%3,%4};"
                 :: "l"(p), "f"(a), "f"(b), "f"(c), "f"(d) : "memory");
}

__device__ __forceinline__ void process_edge(
    float dx, float dy, float dz,
    float gx, float gy, float gz,
    int i, int j)
{
    // i endpoint: 3 force comps + 9 virial comps packed into exactly 3 v4 reds
    float* si = g_scratch + (size_t)i * 12;
    red4(si + 0, gx,      gy,      gz,      dx * gx);
    red4(si + 4, dx * gy, dx * gz, dy * gx, dy * gy);
    red4(si + 8, dy * gz, dz * gx, dz * gy, dz * gz);
    // j endpoint: force -= g
    float* sj = g_scratch + (size_t)j * 12;
    red4(sj + 0, -gx, -gy, -gz, 0.f);
}

// 2 edges per thread, low register footprint -> high occupancy -> more
// outstanding REDs in the LTS queues (R13 showed L2-RMW tput scales with
// resident warps, not per-warp pipelining).
__global__ __launch_bounds__(256) void edge_kernel(
    const float* __restrict__ edge_diff,
    const float* __restrict__ dE,
    const int* __restrict__ edge_idx,
    int n_edges)
{
    int t = blockIdx.x * blockDim.x + threadIdx.x;   // pair index
    int base = 2 * t;
    if (base >= n_edges) return;

    if (base + 1 < n_edges) {
        const float2* diff2 = (const float2*)edge_diff;
        const float2* dE2   = (const float2*)dE;
        const int4*   idx4  = (const int4*)edge_idx;

        // edge_diff[6t..6t+5] = d0x d0y d0z d1x d1y d1z
        float2 a = __ldcs(diff2 + 3 * t + 0);
        float2 b = __ldcs(diff2 + 3 * t + 1);
        float2 c = __ldcs(diff2 + 3 * t + 2);
        float2 p = __ldcs(dE2 + 3 * t + 0);
        float2 q = __ldcs(dE2 + 3 * t + 1);
        float2 r = __ldcs(dE2 + 3 * t + 2);
        int4 ij  = __ldcs(idx4 + t);   // i0 j0 i1 j1

        process_edge(a.x, a.y, b.x, p.x, p.y, q.x, ij.x, ij.y);
        process_edge(b.y, c.x, c.y, q.y, r.x, r.y, ij.z, ij.w);
    } else {
        int e = base;
        process_edge(__ldcs(edge_diff + 3 * e + 0), __ldcs(edge_diff + 3 * e + 1),
                     __ldcs(edge_diff + 3 * e + 2),
                     __ldcs(dE + 3 * e + 0), __ldcs(dE + 3 * e + 1), __ldcs(dE + 3 * e + 2),
                     __ldcs(edge_idx + 2 * e + 0), __ldcs(edge_idx + 2 * e + 1));
    }
}

// 2 atoms per thread. image_idx sorted -> 64-atom warp span almost always image-uniform.
__global__ __launch_bounds__(256) void atom_kernel(
    const int* __restrict__ image_idx,
    float* __restrict__ out,
    int n_atoms)
{
    int t = blockIdx.x * blockDim.x + threadIdx.x;
    int a0 = 2 * t;
    const float4 z4 = make_float4(0.f, 0.f, 0.f, 0.f);

    int my_img = -1;
    float v[9];
#pragma unroll
    for (int k = 0; k < 9; k++) v[k] = 0.f;

    bool active = (a0 < n_atoms);
    if (active) {
        bool has2 = (a0 + 1 < n_atoms);

        float4* s = (float4*)(g_scratch + (size_t)a0 * 12);
        float4 r0 = s[0], r1 = s[1], r2 = s[2];
        float4 r3 = z4, r4 = z4, r5 = z4;
        if (has2) { r3 = s[3]; r4 = s[4]; r5 = s[5]; }

        s[0] = z4; s[1] = z4; s[2] = z4;
        if (has2) { s[3] = z4; s[4] = z4; s[5] = z4; }

        float2* o = (float2*)(out + (size_t)a0 * 3);
        o[0] = make_float2(r0.x, r0.y);
        if (has2) {
            o[1] = make_float2(r0.z, r3.x);
            o[2] = make_float2(r3.y, r3.z);
        } else {
            out[3 * a0 + 2] = r0.z;
        }

        int im0 = image_idx[a0];
        int im1 = has2 ? image_idx[a0 + 1] : im0;

        if (im0 == im1) {
            my_img = im0;
            v[0] = r0.w + r3.w; v[1] = r1.x + r4.x; v[2] = r1.y + r4.y;
            v[3] = r1.z + r4.z; v[4] = r1.w + r4.w; v[5] = r2.x + r5.x;
            v[6] = r2.y + r5.y; v[7] = r2.z + r5.z; v[8] = r2.w + r5.w;
        } else {
            float* ga = g_virial + (size_t)im0 * 12;
            red4(ga + 0, r0.w, r1.x, r1.y, r1.z);
            red4(ga + 4, r1.w, r2.x, r2.y, r2.z);
            red4(ga + 8, r2.w, 0.f, 0.f, 0.f);
            float* gb = g_virial + (size_t)im1 * 12;
            red4(gb + 0, r3.w, r4.x, r4.y, r4.z);
            red4(gb + 4, r4.w, r5.x, r5.y, r5.z);
            red4(gb + 8, r5.w, 0.f, 0.f, 0.f);
        }
    }

    int lane = threadIdx.x & 31;
    int img0 = __shfl_sync(0xFFFFFFFFu, my_img, 0);
    bool uniform = __all_sync(0xFFFFFFFFu, my_img == img0) && (img0 >= 0);

    if (uniform) {
        // 4-stage butterfly (16,8,4,2): lane0 = even-lane sum, lane1 = odd-lane sum
#pragma unroll
        for (int k = 0; k < 9; k++) {
#pragma unroll
            for (int off = 16; off > 1; off >>= 1)
                v[k] += __shfl_xor_sync(0xFFFFFFFFu, v[k], off);
        }
        if (lane < 2) {
            float* g = g_virial + (size_t)img0 * 12;
            red4(g + 0, v[0], v[1], v[2], v[3]);
            red4(g + 4, v[4], v[5], v[6], v[7]);
            red4(g + 8, v[8], 0.f, 0.f, 0.f);
        }
    } else if (my_img >= 0) {
        float* g = g_virial + (size_t)my_img * 12;
        red4(g + 0, v[0], v[1], v[2], v[3]);
        red4(g + 4, v[4], v[5], v[6], v[7]);
        red4(g + 8, v[8], 0.f, 0.f, 0.f);
    }
}

__global__ void finalize_kernel(
    const float* __restrict__ cell,
    float* __restrict__ out,
    int n_atoms, int n_images)
{
    int i = threadIdx.x;
    if (i >= n_images) return;

    const float* c = cell + i * 9;
    float a0 = c[0], a1 = c[1], a2 = c[2];
    float b0 = c[3], b1 = c[4], b2 = c[5];
    float c0 = c[6], c1 = c[7], c2 = c[8];
    float x0 = b1 * c2 - b2 * c1;
    float x1 = b2 * c0 - b0 * c2;
    float x2 = b0 * c1 - b1 * c0;
    float vol = a0 * x0 + a1 * x1 + a2 * x2;
    float inv = -1.0f / vol;

    float* gv = g_virial + (size_t)i * 12;
    float* vir_out    = out + (size_t)n_atoms * 3 + (size_t)i * 9;
    float* stress_out = out + (size_t)n_atoms * 3 + (size_t)n_images * 9 + (size_t)i * 9;
    float vv[9];
#pragma unroll
    for (int k = 0; k < 9; k++) vv[k] = gv[k];
#pragma unroll
    for (int k = 0; k < 9; k++) {
        vir_out[k] = vv[k];
        stress_out[k] = vv[k] * inv;
    }
    float4* gv4 = (float4*)gv;
    gv4[0] = make_float4(0.f, 0.f, 0.f, 0.f);
    gv4[1] = make_float4(0.f, 0.f, 0.f, 0.f);
    gv4[2] = make_float4(0.f, 0.f, 0.f, 0.f);
}

extern "C" void kernel_launch(void* const* d_in, const int* in_sizes, int n_in,
                              void* d_out, int out_size)
{
    const float* edge_diff = (const float*)d_in[0];
    const float* dE        = (const float*)d_in[1];
    const float* cell      = (const float*)d_in[2];
    const int*   edge_idx  = (const int*)d_in[3];
    const int*   image_idx = (const int*)d_in[4];

    int n_edges  = in_sizes[0] / 3;
    int n_atoms  = in_sizes[4];
    int n_images = in_sizes[2] / 9;
    float* out = (float*)d_out;

    int n_pairs = (n_edges + 1) / 2;
    edge_kernel<<<(n_pairs + 255) / 256, 256>>>(edge_diff, dE, edge_idx, n_edges);

    int n_t = (n_atoms + 1) / 2;
    atom_kernel<<<(n_t + 255) / 256, 256>>>(image_idx, out, n_atoms);

    finalize_kernel<<<1, 128>>>(cell, out, n_atoms, n_images);
}

// round 15
// speedup vs baseline: 1.1324x; 1.0018x over previous
#include <cuda_runtime.h>
#include <cstdint>

#define N_ATOMS_MAX 200000
#define N_IMAGES_MAX 128

// Zero-initialized at module load. Every run restores the all-zero invariant:
//  - atom_kernel writes zeros back to each scratch row it consumes
//  - the last atom_kernel block re-zeros g_virial and resets g_counter
__device__ __align__(16) float g_scratch[(size_t)N_ATOMS_MAX * 12];
__device__ __align__(16) float g_virial[N_IMAGES_MAX * 12];
__device__ int g_counter;

__device__ __forceinline__ void red4(float* p, float a, float b, float c, float d) {
    asm volatile("red.global.add.v4.f32 [%0], {%1,%2,%3,%4};"
                 :: "l"(p), "f"(a), "f"(b), "f"(c), "f"(d) : "memory");
}

__device__ __forceinline__ void process_edge(
    float dx, float dy, float dz,
    float gx, float gy, float gz,
    int i, int j)
{
    // i endpoint: 3 force comps + 9 virial comps packed into exactly 3 v4 reds
    float* si = g_scratch + (size_t)i * 12;
    red4(si + 0, gx,      gy,      gz,      dx * gx);
    red4(si + 4, dx * gy, dx * gz, dy * gx, dy * gy);
    red4(si + 8, dy * gz, dz * gx, dz * gy, dz * gz);
    // j endpoint: force -= g
    float* sj = g_scratch + (size_t)j * 12;
    red4(sj + 0, -gx, -gy, -gz, 0.f);
}

// 2 edges per thread, low register footprint -> high occupancy. L2-RMW is the
// ceiling (~85% at >=40% occ, verified R12-R14); this kernel is at the floor
// of 4 red4/edge and stays unchanged.
__global__ __launch_bounds__(256) void edge_kernel(
    const float* __restrict__ edge_diff,
    const float* __restrict__ dE,
    const int* __restrict__ edge_idx,
    int n_edges)
{
    int t = blockIdx.x * blockDim.x + threadIdx.x;   // pair index
    int base = 2 * t;
    if (base >= n_edges) return;

    if (base + 1 < n_edges) {
        const float2* diff2 = (const float2*)edge_diff;
        const float2* dE2   = (const float2*)dE;
        const int4*   idx4  = (const int4*)edge_idx;

        float2 a = __ldcs(diff2 + 3 * t + 0);
        float2 b = __ldcs(diff2 + 3 * t + 1);
        float2 c = __ldcs(diff2 + 3 * t + 2);
        float2 p = __ldcs(dE2 + 3 * t + 0);
        float2 q = __ldcs(dE2 + 3 * t + 1);
        float2 r = __ldcs(dE2 + 3 * t + 2);
        int4 ij  = __ldcs(idx4 + t);   // i0 j0 i1 j1

        process_edge(a.x, a.y, b.x, p.x, p.y, q.x, ij.x, ij.y);
        process_edge(b.y, c.x, c.y, q.y, r.x, r.y, ij.z, ij.w);
    } else {
        int e = base;
        process_edge(__ldcs(edge_diff + 3 * e + 0), __ldcs(edge_diff + 3 * e + 1),
                     __ldcs(edge_diff + 3 * e + 2),
                     __ldcs(dE + 3 * e + 0), __ldcs(dE + 3 * e + 1), __ldcs(dE + 3 * e + 2),
                     __ldcs(edge_idx + 2 * e + 0), __ldcs(edge_idx + 2 * e + 1));
    }
}

// 2 atoms per thread + fused finalize tail (last-block-done). 391 blocks, so
// the per-block fence/counter cost is negligible; saves the 1-block finalize
// kernel's ~5us of graph-node overhead plus a launch gap.
__global__ __launch_bounds__(256) void atom_kernel(
    const int* __restrict__ image_idx,
    const float* __restrict__ cell,
    float* __restrict__ out,
    int n_atoms, int n_images)
{
    int t = blockIdx.x * blockDim.x + threadIdx.x;
    int a0 = 2 * t;
    const float4 z4 = make_float4(0.f, 0.f, 0.f, 0.f);

    int my_img = -1;
    float v[9];
#pragma unroll
    for (int k = 0; k < 9; k++) v[k] = 0.f;

    bool active = (a0 < n_atoms);
    if (active) {
        bool has2 = (a0 + 1 < n_atoms);

        float4* s = (float4*)(g_scratch + (size_t)a0 * 12);
        float4 r0 = s[0], r1 = s[1], r2 = s[2];
        float4 r3 = z4, r4 = z4, r5 = z4;
        if (has2) { r3 = s[3]; r4 = s[4]; r5 = s[5]; }

        s[0] = z4; s[1] = z4; s[2] = z4;
        if (has2) { s[3] = z4; s[4] = z4; s[5] = z4; }

        float2* o = (float2*)(out + (size_t)a0 * 3);
        o[0] = make_float2(r0.x, r0.y);
        if (has2) {
            o[1] = make_float2(r0.z, r3.x);
            o[2] = make_float2(r3.y, r3.z);
        } else {
            out[3 * a0 + 2] = r0.z;
        }

        int im0 = image_idx[a0];
        int im1 = has2 ? image_idx[a0 + 1] : im0;

        if (im0 == im1) {
            my_img = im0;
            v[0] = r0.w + r3.w; v[1] = r1.x + r4.x; v[2] = r1.y + r4.y;
            v[3] = r1.z + r4.z; v[4] = r1.w + r4.w; v[5] = r2.x + r5.x;
            v[6] = r2.y + r5.y; v[7] = r2.z + r5.z; v[8] = r2.w + r5.w;
        } else {
            float* ga = g_virial + (size_t)im0 * 12;
            red4(ga + 0, r0.w, r1.x, r1.y, r1.z);
            red4(ga + 4, r1.w, r2.x, r2.y, r2.z);
            red4(ga + 8, r2.w, 0.f, 0.f, 0.f);
            float* gb = g_virial + (size_t)im1 * 12;
            red4(gb + 0, r3.w, r4.x, r4.y, r4.z);
            red4(gb + 4, r4.w, r5.x, r5.y, r5.z);
            red4(gb + 8, r5.w, 0.f, 0.f, 0.f);
        }
    }

    int lane = threadIdx.x & 31;
    int img0 = __shfl_sync(0xFFFFFFFFu, my_img, 0);
    bool uniform = __all_sync(0xFFFFFFFFu, my_img == img0) && (img0 >= 0);

    if (uniform) {
        // 4-stage butterfly (16,8,4,2): lane0 = even-lane sum, lane1 = odd-lane sum
#pragma unroll
        for (int k = 0; k < 9; k++) {
#pragma unroll
            for (int off = 16; off > 1; off >>= 1)
                v[k] += __shfl_xor_sync(0xFFFFFFFFu, v[k], off);
        }
        if (lane < 2) {
            float* g = g_virial + (size_t)img0 * 12;
            red4(g + 0, v[0], v[1], v[2], v[3]);
            red4(g + 4, v[4], v[5], v[6], v[7]);
            red4(g + 8, v[8], 0.f, 0.f, 0.f);
        }
    } else if (my_img >= 0) {
        float* g = g_virial + (size_t)my_img * 12;
        red4(g + 0, v[0], v[1], v[2], v[3]);
        red4(g + 4, v[4], v[5], v[6], v[7]);
        red4(g + 8, v[8], 0.f, 0.f, 0.f);
    }

    // Last-block-done finalize: virial -> out, stress, restore invariants
    __threadfence();
    __shared__ int is_last;
    if (threadIdx.x == 0) {
        int old = atomicAdd(&g_counter, 1);
        is_last = (old == (int)gridDim.x - 1) ? 1 : 0;
    }
    __syncthreads();
    if (is_last) {
        __threadfence();   // acquire: make all blocks' reds visible
        int i = threadIdx.x;
        if (i < n_images) {
            const float* c = cell + i * 9;
            float a0c = c[0], a1 = c[1], a2 = c[2];
            float b0 = c[3], b1 = c[4], b2 = c[5];
            float c0 = c[6], c1 = c[7], c2 = c[8];
            float x0 = b1 * c2 - b2 * c1;
            float x1 = b2 * c0 - b0 * c2;
            float x2 = b0 * c1 - b1 * c0;
            float vol = a0c * x0 + a1 * x1 + a2 * x2;
            float inv = -1.0f / vol;

            float* gv = g_virial + (size_t)i * 12;
            float* vir_out    = out + (size_t)n_atoms * 3 + (size_t)i * 9;
            float* stress_out = out + (size_t)n_atoms * 3 + (size_t)n_images * 9 + (size_t)i * 9;
            float vv[9];
#pragma unroll
            for (int k = 0; k < 9; k++) vv[k] = gv[k];
#pragma unroll
            for (int k = 0; k < 9; k++) {
                vir_out[k] = vv[k];
                stress_out[k] = vv[k] * inv;
            }
            // restore zero invariant
            float4* gv4 = (float4*)gv;
            gv4[0] = z4; gv4[1] = z4; gv4[2] = z4;
        }
        if (threadIdx.x == 0) g_counter = 0;
    }
}

extern "C" void kernel_launch(void* const* d_in, const int* in_sizes, int n_in,
                              void* d_out, int out_size)
{
    const float* edge_diff = (const float*)d_in[0];
    const float* dE        = (const float*)d_in[1];
    const float* cell      = (const float*)d_in[2];
    const int*   edge_idx  = (const int*)d_in[3];
    const int*   image_idx = (const int*)d_in[4];

    int n_edges  = in_sizes[0] / 3;
    int n_atoms  = in_sizes[4];
    int n_images = in_sizes[2] / 9;
    float* out = (float*)d_out;

    int n_pairs = (n_edges + 1) / 2;
    edge_kernel<<<(n_pairs + 255) / 256, 256>>>(edge_diff, dE, edge_idx, n_edges);

    int n_t = (n_atoms + 1) / 2;
    atom_kernel<<<(n_t + 255) / 256, 256>>>(image_idx, cell, out, n_atoms, n_images);
}